// round 6
// baseline (speedup 1.0000x reference)
#include <cuda_runtime.h>
#include <cstdint>

// Problem constants:
// B=32, N=32, P0=16, P1=32, P2=16, R=3, D=8, V=2
// num_in = 112, RD = 24
// out per b: 16 (null) + 1024 (unary) + 32*31*16 (binary) = 16912

#define RD 24
#define NUMIN 112

typedef unsigned long long u64;

// -------- device scratch --------
__device__ float g_BW[384 * 4];            // packed binary weights (float4 as 4 floats)
__device__ float g_PU1[32 * RD * 32];      // [b][rd][i]  PN*U1*sigmoid(or)
__device__ float g_U2[32 * RD * 32];       // [b][rd][j]  U2
__device__ float g_partB[32 * 8];          // per (b, ig) partial nullary product
__device__ unsigned int g_ctr = 0;

// -------- packed f32x2 helpers (Blackwell) --------
__device__ __forceinline__ u64 pk2(float a, float b) {
    u64 r; asm("mov.b64 %0, {%1,%2};" : "=l"(r) : "f"(a), "f"(b)); return r;
}
__device__ __forceinline__ void upk2(u64 v, float& a, float& b) {
    asm("mov.b64 {%0,%1}, %2;" : "=f"(a), "=f"(b) : "l"(v));
}
__device__ __forceinline__ u64 fma2(u64 a, u64 b, u64 c) {
    u64 d; asm("fma.rn.f32x2 %0, %1, %2, %3;" : "=l"(d) : "l"(a), "l"(b), "l"(c)); return d;
}
__device__ __forceinline__ u64 mul2(u64 a, u64 b) {
    u64 d; asm("mul.rn.f32x2 %0, %1, %2;" : "=l"(d) : "l"(a), "l"(b)); return d;
}
__device__ __forceinline__ void lds_wc(u64& w, u64& c, uint32_t addr) {
    asm volatile("ld.shared.v2.u64 {%0,%1}, [%2];" : "=l"(w), "=l"(c) : "r"(addr));
}
__device__ __forceinline__ uint32_t smem_u32(const void* p) {
    uint32_t a;
    asm("{ .reg .u64 t; cvta.to.shared.u64 t, %1; cvt.u32.u64 %0, t; }" : "=r"(a) : "l"(p));
    return a;
}

// ============================================================================
// k1: weights + per-(b,i) partial products. grid = 32 (b), block = 768.
// Thread t: one U2 item (j = t&31, rd = t>>5) and one PU1 item (i = t&31).
// Block 0 additionally publishes the packed binary weight table.
// ============================================================================
__global__ __launch_bounds__(768, 1)
void k1(const float* __restrict__ nul, const float* __restrict__ una,
        const float* __restrict__ andk, const float* __restrict__ ork) {
    __shared__ float2 sWC[RD * NUMIN];   // (w = p0-p1, c = p1+p2)
    __shared__ float  sU[32 * 32];       // [k][i] transposed
    __shared__ float  sN[16];
    __shared__ float  sOK[24];

    const int b = blockIdx.x;
    const int t = threadIdx.x;

    // softmax (fast math)
    for (int idx = t; idx < RD * NUMIN; idx += 768) {
        float a0 = andk[idx * 3 + 0];
        float a1 = andk[idx * 3 + 1];
        float a2 = andk[idx * 3 + 2];
        float e0 = __expf(a0), e1 = __expf(a1), e2 = __expf(a2);
        float inv = __fdividef(1.0f, e0 + e1 + e2);
        sWC[idx] = make_float2((e0 - e1) * inv, (e1 + e2) * inv);
    }
    for (int idx = t; idx < 1024; idx += 768) {
        int ii = idx >> 5, k = idx & 31;
        sU[k * 32 + ii] = una[b * 1024 + idx];
    }
    if (t < 16) sN[t] = nul[b * 16 + t];
    else if (t >= 32 && t < 56) {
        float x = ork[t - 32];
        sOK[t - 32] = __fdividef(1.0f, 1.0f + __expf(-x));
    }
    __syncthreads();

    // block 0: publish packed binary weights
    if (b == 0 && t < 384) {
        int kk = t / 12, rdp = t % 12;
        int slice = (kk < 16) ? (80 + kk) : (96 + kk - 16);
        float2 lo = sWC[(2 * rdp)     * NUMIN + slice];
        float2 hi = sWC[(2 * rdp + 1) * NUMIN + slice];
        ((float4*)g_BW)[t] = make_float4(lo.x, hi.x, lo.y, hi.y);
    }

    const int obj = t & 31;       // i or j
    const int rd  = t >> 5;       // 0..23

    // U2[b][rd][j], 4-way split chain
    {
        const float2* wc = sWC + rd * NUMIN + 48;
        float pa = 1.0f, pb = 1.0f, pc = 1.0f, pd = 1.0f;
#pragma unroll
        for (int k = 0; k < 8; k++) {
            float2 w0 = wc[k],      w1 = wc[8 + k];
            float2 w2 = wc[16 + k], w3 = wc[24 + k];
            pa *= fmaf(sU[k * 32 + obj],        w0.x, w0.y);
            pb *= fmaf(sU[(8 + k) * 32 + obj],  w1.x, w1.y);
            pc *= fmaf(sU[(16 + k) * 32 + obj], w2.x, w2.y);
            pd *= fmaf(sU[(24 + k) * 32 + obj], w3.x, w3.y);
        }
        g_U2[(b * RD + rd) * 32 + obj] = (pa * pb) * (pc * pd);
    }
    // PU1[b][rd][i] = PN * U1 * sigmoid(or)
    {
        const float2* wc = sWC + rd * NUMIN;
        float pa = 1.0f, pb = 1.0f, pc = 1.0f, pd = 1.0f;
#pragma unroll
        for (int k = 0; k < 8; k++) {
            float2 w0 = wc[k], w1 = wc[8 + k];
            pa *= fmaf(sN[k],     w0.x, w0.y);
            pb *= fmaf(sN[8 + k], w1.x, w1.y);
        }
#pragma unroll
        for (int k = 0; k < 16; k++) {
            float2 w0 = wc[16 + k], w1 = wc[32 + k];
            pc *= fmaf(sU[k * 32 + obj],        w0.x, w0.y);
            pd *= fmaf(sU[(16 + k) * 32 + obj], w1.x, w1.y);
        }
        g_PU1[(b * RD + rd) * 32 + obj] = ((pa * pb) * (pc * pd)) * sOK[rd];
    }
}

// ============================================================================
// k2: hot kernel. grid = (8 ig, 32 b), block = 256 = 8 warps.
// wid: half = wid>>2, i_loc = wid&3, i = ig*4+i_loc, lane = jj.
// half0: kk 0..15 (x1 row) + epilogue; half1: kk 16..31 (x2 row).
// ============================================================================
__global__ __launch_bounds__(256, 2)
void k2(const float* __restrict__ nul, const float* __restrict__ una,
        const float* __restrict__ binp, float* __restrict__ out) {
    __shared__ float4 sBW[384];           // packed binary weights [kk][rdp]
    __shared__ float  sU2[32 * 25];       // U2[j][rd]
    __shared__ float  sPU1[4 * 24];       // PU1 for local 4 i's
    __shared__ u64    sAcc[4 * 32 * 12];  // half1 partials (12 KB)
    __shared__ float  sWarpR0[4];
    __shared__ int    sIsLast;

    const int ig   = blockIdx.x;          // 0..7
    const int b    = blockIdx.y;          // 0..31
    const int t    = threadIdx.x;         // 0..255
    const int wid  = t >> 5;              // 0..7
    const int lane = t & 31;
    const int half  = wid >> 2;           // 0 or 1
    const int i_loc = wid & 3;
    const int i     = ig * 4 + i_loc;

    const int  jj     = lane;
    const bool active = (jj < 31);
    const int  jj_s   = active ? jj : 0;
    const int  j      = jj_s + (jj_s >= i);
    const int  ip     = i - (jj_s < i);

    // ---- hoisted global loads ----
    float xs[16];
    {
        const size_t row = half ? (((size_t)b * 32 + j) * 31 + ip)
                                : (((size_t)b * 32 + i) * 31 + jj_s);
        const float4* p = (const float4*)(binp + row * 16);
        float4 v[4];
#pragma unroll
        for (int q = 0; q < 4; q++) v[q] = p[q];
#pragma unroll
        for (int q = 0; q < 4; q++) {
            xs[4 * q + 0] = v[q].x; xs[4 * q + 1] = v[q].y;
            xs[4 * q + 2] = v[q].z; xs[4 * q + 3] = v[q].w;
        }
    }
    const float uk = (half == 0) ? una[(size_t)b * 1024 + i * 32 + lane] : 0.0f;

    // ---- prologue: pure loads into shared ----
    {
        const float4* gbw = (const float4*)g_BW;
        sBW[t]       = gbw[t];
        sBW[t + 128] = gbw[t + 128];
        sBW[t + 256] = gbw[t + 256];
    }
    {
        // 768 U2 values: item = rd*32 + j (coalesced read)
        int item = t;
        int rd = item >> 5, jx = item & 31;
        sU2[jx * 25 + rd] = g_U2[b * 768 + item];
        item = t + 256; rd = item >> 5; jx = item & 31;
        sU2[jx * 25 + rd] = g_U2[b * 768 + item];
        item = t + 512; rd = item >> 5; jx = item & 31;
        sU2[jx * 25 + rd] = g_U2[b * 768 + item];
    }
    if (t < 96) {
        int rd = t >> 2, il = t & 3;
        sPU1[il * 24 + rd] = g_PU1[(b * RD + rd) * 32 + ig * 4 + il];
    }
    __syncthreads();

    // ---- main loop: 16 kk per half ----
    u64 acc[12];
    if (half == 0) {
#pragma unroll
        for (int rdp = 0; rdp < 12; rdp++) {
            float lo = sPU1[i_loc * 24 + 2 * rdp]     * sU2[j * 25 + 2 * rdp];
            float hi = sPU1[i_loc * 24 + 2 * rdp + 1] * sU2[j * 25 + 2 * rdp + 1];
            acc[rdp] = pk2(lo, hi);
        }
    } else {
        u64 one = pk2(1.0f, 1.0f);
#pragma unroll
        for (int rdp = 0; rdp < 12; rdp++) acc[rdp] = one;
    }

    const uint32_t sb = smem_u32(sBW) + (uint32_t)(half * 16 * 12 * 16);
#pragma unroll
    for (int kl = 0; kl < 16; kl++) {
        u64 xx = pk2(xs[kl], xs[kl]);
#pragma unroll
        for (int rdp = 0; rdp < 12; rdp++) {
            u64 w, c;
            lds_wc(w, c, sb + (uint32_t)((kl * 12 + rdp) * 16));
            acc[rdp] = mul2(acc[rdp], fma2(xx, w, c));
        }
    }

    // ---- exchange: half1 -> dedicated shared buffer ----
    if (half == 1) {
        u64* dst = sAcc + ((size_t)i_loc * 32 + jj) * 12;
#pragma unroll
        for (int rdp = 0; rdp < 12; rdp++) dst[rdp] = acc[rdp];
    }
    __syncthreads();

    if (half == 0) {
        const u64* src = sAcc + ((size_t)i_loc * 32 + jj) * 12;
        float tv[24];
#pragma unroll
        for (int rdp = 0; rdp < 12; rdp++) {
            u64 m = mul2(acc[rdp], src[rdp]);
            float lo, hi;
            upk2(m, lo, hi);
            tv[2 * rdp]     = 1.0f - lo;
            tv[2 * rdp + 1] = 1.0f - hi;
        }
        float pr0 = 1.0f, pr1 = 1.0f, pr2 = 1.0f;
#pragma unroll
        for (int d = 0; d < 8; d++) {
            pr0 *= tv[d];
            pr1 *= tv[8 + d];
            pr2 *= tv[16 + d];
        }

        // binary output row (channels 0..14 copy, channel 15 merged)
        if (active) {
            float4 o[4];
#pragma unroll
            for (int q = 0; q < 4; q++) {
                o[q].x = xs[4 * q + 0]; o[q].y = xs[4 * q + 1];
                o[q].z = xs[4 * q + 2]; o[q].w = xs[4 * q + 3];
            }
            o[3].w = 1.0f - (1.0f - xs[15]) * pr2;
            float4* ob = (float4*)(out + (size_t)b * 16912 + 1040 + (size_t)(i * 31 + jj) * 16);
#pragma unroll
            for (int q = 0; q < 4; q++) ob[q] = o[q];
        } else {
            pr0 = 1.0f;
            pr1 = 1.0f;
        }

        float r0 = pr0, r1 = pr1;
#pragma unroll
        for (int s = 16; s > 0; s >>= 1) {
            r0 *= __shfl_xor_sync(0xFFFFFFFFu, r0, s);
            r1 *= __shfl_xor_sync(0xFFFFFFFFu, r1, s);
        }

        float uv = (lane < 31) ? uk : (1.0f - (1.0f - uk) * r1);
        out[(size_t)b * 16912 + 16 + i * 32 + lane] = uv;

        if (lane == 0) sWarpR0[i_loc] = r0;
    }
    __syncthreads();

    // ---- last-block nullary epilogue ----
    if (t == 0) {
        float p = sWarpR0[0] * sWarpR0[1] * sWarpR0[2] * sWarpR0[3];
        __stcg(&g_partB[b * 8 + ig], p);
        __threadfence();
        unsigned int ticket = atomicAdd(&g_ctr, 1u);
        sIsLast = (ticket == 255u) ? 1 : 0;
    }
    __syncthreads();

    if (sIsLast) {
        __threadfence();
        for (int item = t; item < 512; item += 256) {
            int bb = item >> 4, c = item & 15;
            float v = nul[bb * 16 + c];
            if (c == 15) {
                float p = 1.0f;
#pragma unroll
                for (int g = 0; g < 8; g++) p *= __ldcg(&g_partB[bb * 8 + g]);
                v = 1.0f - (1.0f - v) * p;
            }
            out[(size_t)bb * 16912 + c] = v;
        }
        if (t == 0) atomicExch(&g_ctr, 0u);
    }
}

// ============================================================================
extern "C" void kernel_launch(void* const* d_in, const int* in_sizes, int n_in,
                              void* d_out, int out_size) {
    // Identify the 5 inputs by rank order of element count (all distinct):
    //   ork (24) < nul (512) < andk (8064) < una (32768) < binp (507904)
    int order[5] = {0, 1, 2, 3, 4};
    for (int a = 1; a < 5 && a < n_in; a++) {
        int key = order[a];
        int ks = in_sizes[key];
        int bpos = a - 1;
        while (bpos >= 0 && in_sizes[order[bpos]] > ks) {
            order[bpos + 1] = order[bpos];
            bpos--;
        }
        order[bpos + 1] = key;
    }
    const float* ork  = (const float*)d_in[order[0]];
    const float* nul  = (const float*)d_in[order[1]];
    const float* andk = (const float*)d_in[order[2]];
    const float* una  = (const float*)d_in[order[3]];
    const float* binp = (const float*)d_in[order[4]];
    float* out = (float*)d_out;

    k1<<<32, 768>>>(nul, una, andk, ork);
    k2<<<dim3(8, 32), 256>>>(nul, una, binp, out);
}